// round 4
// baseline (speedup 1.0000x reference)
#include <cuda_runtime.h>
#include <math.h>

#define MAXN 100000
#define MAXE 1600000
#define MAXB 256
#define H 64

// ---------------- scratch (static device globals; no allocation) ----------------
__device__ float  g_h[MAXN * H];        // node features
__device__ float  g_hW[MAXN * H];       // h @ conv_w[:64] + b
__device__ float4 g_stats[MAXN];        // (sum, sumsq, dot We0, dot We1) of hW row
__device__ int    g_deg[MAXN];          // incoming degree
__device__ int    g_off[MAXN + 1];      // CSR offsets
__device__ int    g_cur[MAXN];          // fill cursors
__device__ int    g_csr_src[MAXE];
__device__ float2 g_csr_ea[MAXE];
__device__ int    g_bsum[512];          // scan partials
__device__ float  g_lc[8];              // per-layer constants
__device__ float  g_pool[MAXB * H];
__device__ int    g_cnt[MAXB];

__device__ __forceinline__ float warp_sum(float v) {
    #pragma unroll
    for (int o = 16; o > 0; o >>= 1) v += __shfl_xor_sync(0xffffffffu, v, o);
    return v;
}
// reduction across a 16-lane half (offsets stay inside the half)
__device__ __forceinline__ float rsum16(float v) {
    #pragma unroll
    for (int o = 8; o > 0; o >>= 1) v += __shfl_xor_sync(0xffffffffu, v, o);
    return v;
}
__device__ __forceinline__ float gelu_exact(float v) {
    return 0.5f * v * (1.0f + erff(v * 0.7071067811865476f));
}
// fast gelu via HW tanh (MUFU.TANH); |err| vs exact erf-gelu ~3e-4 abs
__device__ __forceinline__ float gelu_fast(float x) {
    float x2 = x * x;
    float inner = fmaf(0.0356774081f, x2, 0.7978845608f);
    float u = x * inner;
    float t;
    asm("tanh.approx.f32 %0, %1;" : "=f"(t) : "f"(u));
    float hx = 0.5f * x;
    return fmaf(hx, t, hx);
}

// ---------------- zero init ----------------
__global__ void zero_kernel(int N, int B) {
    int i = blockIdx.x * blockDim.x + threadIdx.x;
    if (i < N) { g_deg[i] = 0; g_cur[i] = 0; }
    if (i < B * H) g_pool[i] = 0.0f;
    if (i < B) g_cnt[i] = 0;
}

// ---------------- node embedding MLP (warp per node) ----------------
__global__ __launch_bounds__(256) void node_embed_kernel(
    const float* __restrict__ x,
    const float* __restrict__ w1, const float* __restrict__ b1,
    const float* __restrict__ g1, const float* __restrict__ be1,
    const float* __restrict__ w2, const float* __restrict__ b2,
    const float* __restrict__ g2, const float* __restrict__ be2, int N)
{
    __shared__ float ws[H * H];
    int t = threadIdx.x;
    for (int i = t; i < H * H; i += 256) ws[i] = w2[i];
    __syncthreads();
    int node = blockIdx.x * 8 + (t >> 5);
    int lane = t & 31;
    if (node >= N) return;
    int c0 = 2 * lane, c1 = c0 + 1;
    float x0 = x[node * 2], x1 = x[node * 2 + 1];
    float p0 = fmaf(x1, w1[H + c0], fmaf(x0, w1[c0], b1[c0]));
    float p1 = fmaf(x1, w1[H + c1], fmaf(x0, w1[c1], b1[c1]));
    float s = warp_sum(p0 + p1);
    float q = warp_sum(p0 * p0 + p1 * p1);
    float mu = s * (1.0f / H);
    float r  = rsqrtf(q * (1.0f / H) - mu * mu + 1e-5f);
    float a0 = gelu_exact((p0 - mu) * r * g1[c0] + be1[c0]);
    float a1 = gelu_exact((p1 - mu) * r * g1[c1] + be1[c1]);
    float acc0 = b2[c0], acc1 = b2[c1];
    #pragma unroll
    for (int k = 0; k < 32; k++) {
        float u = __shfl_sync(0xffffffffu, a0, k);
        float v = __shfl_sync(0xffffffffu, a1, k);
        const float* r0 = &ws[(2 * k) * H];
        const float* r1 = &ws[(2 * k + 1) * H];
        acc0 = fmaf(u, r0[c0], acc0); acc0 = fmaf(v, r1[c0], acc0);
        acc1 = fmaf(u, r0[c1], acc1); acc1 = fmaf(v, r1[c1], acc1);
    }
    s = warp_sum(acc0 + acc1);
    q = warp_sum(acc0 * acc0 + acc1 * acc1);
    mu = s * (1.0f / H);
    r  = rsqrtf(q * (1.0f / H) - mu * mu + 1e-5f);
    g_h[node * H + c0] = gelu_exact((acc0 - mu) * r * g2[c0] + be2[c0]);
    g_h[node * H + c1] = gelu_exact((acc1 - mu) * r * g2[c1] + be2[c1]);
}

// ---------------- CSR build ----------------
__global__ void count_deg_kernel(const int* __restrict__ ei, int E) {
    int e = blockIdx.x * blockDim.x + threadIdx.x;
    if (e < E) atomicAdd(&g_deg[ei[E + e]], 1);
}

__global__ void scan_local_kernel(int N) {
    __shared__ int wsums[16];
    int t = threadIdx.x, lane = t & 31, w = t >> 5;
    int i = blockIdx.x * 512 + t;
    int x = (i < N) ? g_deg[i] : 0;
    int v = x;
    #pragma unroll
    for (int o = 1; o < 32; o <<= 1) { int n = __shfl_up_sync(0xffffffffu, v, o); if (lane >= o) v += n; }
    if (lane == 31) wsums[w] = v;
    __syncthreads();
    if (w == 0) {
        int s = (lane < 16) ? wsums[lane] : 0;
        #pragma unroll
        for (int o = 1; o < 16; o <<= 1) { int n = __shfl_up_sync(0xffffffffu, s, o); if (lane >= o) s += n; }
        if (lane < 16) wsums[lane] = s;
    }
    __syncthreads();
    int off = (w > 0) ? wsums[w - 1] : 0;
    int incl = v + off;
    if (i < N) g_off[i] = incl - x;
    if (t == 511) g_bsum[blockIdx.x] = incl;
}

__global__ void scan_bsum_kernel(int nblk) {
    __shared__ int wsums[8];
    int t = threadIdx.x, lane = t & 31, w = t >> 5;
    int x = (t < nblk) ? g_bsum[t] : 0;
    int v = x;
    #pragma unroll
    for (int o = 1; o < 32; o <<= 1) { int n = __shfl_up_sync(0xffffffffu, v, o); if (lane >= o) v += n; }
    if (lane == 31) wsums[w] = v;
    __syncthreads();
    if (w == 0) {
        int s = (lane < 8) ? wsums[lane] : 0;
        #pragma unroll
        for (int o = 1; o < 8; o <<= 1) { int n = __shfl_up_sync(0xffffffffu, s, o); if (lane >= o && lane < 8) s += n; }
        if (lane < 8) wsums[lane] = s;
    }
    __syncthreads();
    int off = (w > 0) ? wsums[w - 1] : 0;
    if (t < nblk) g_bsum[t] = v + off - x;   // exclusive
}

__global__ void scan_add_kernel(int N, int E) {
    int i = blockIdx.x * 512 + threadIdx.x;
    if (i < N) g_off[i] += g_bsum[blockIdx.x];
    if (i == 0) g_off[N] = E;
}

__global__ void fill_csr_kernel(const int* __restrict__ ei, const float* __restrict__ ea, int E) {
    int e = blockIdx.x * blockDim.x + threadIdx.x;
    if (e >= E) return;
    int d = ei[E + e];
    int p = g_off[d] + atomicAdd(&g_cur[d], 1);
    g_csr_src[p] = ei[e];
    g_csr_ea[p] = *(const float2*)&ea[2 * e];
}

// ---------------- per-layer: constants ----------------
__global__ void prep_layer_kernel(const float* __restrict__ cw) {
    int lane = threadIdx.x;
    float a0 = cw[64 * H + 2 * lane], a1 = cw[64 * H + 2 * lane + 1];
    float b0 = cw[65 * H + 2 * lane], b1 = cw[65 * H + 2 * lane + 1];
    float SW0 = warp_sum(a0 + a1);
    float SW1 = warp_sum(b0 + b1);
    float Q0  = warp_sum(a0 * a0 + a1 * a1);
    float Q1  = warp_sum(b0 * b0 + b1 * b1);
    float D01 = warp_sum(a0 * b0 + a1 * b1);
    if (lane == 0) { g_lc[0] = SW0; g_lc[1] = SW1; g_lc[2] = Q0; g_lc[3] = Q1; g_lc[4] = D01; }
}

// ---------------- per-layer: hW = h@W + b, plus LN stats ----------------
// warp = 2 nodes (one per 16-lane half); lane owns 4 channels (float4).
__global__ __launch_bounds__(256) void hw_stats_kernel(
    const float* __restrict__ cw, const float* __restrict__ cb, int N)
{
    __shared__ float ws[H * H];      // 16 KB weights
    __shared__ float hs[8][2][H];    // staged h rows
    int t = threadIdx.x;
    {   // cooperative weight load: 4096 floats = 1024 float4
        const float4* cw4 = (const float4*)cw;
        float4* ws4 = (float4*)ws;
        #pragma unroll
        for (int i = 0; i < 4; i++) ws4[t + 256 * i] = cw4[t + 256 * i];
    }
    int wid = t >> 5, lane = t & 31, half = lane >> 4, hl = lane & 15;
    int node = blockIdx.x * 16 + wid * 2 + half;
    bool valid = node < N;
    int c = hl * 4;
    float4 h4 = make_float4(0.f, 0.f, 0.f, 0.f);
    if (valid) h4 = *(const float4*)&g_h[node * H + c];
    *(float4*)&hs[wid][half][c] = h4;
    __syncthreads();

    float4 acc = *(const float4*)&cb[c];
    const float* hrow = hs[wid][half];
    #pragma unroll
    for (int k4 = 0; k4 < 16; k4++) {
        float4 a = *(const float4*)&hrow[k4 * 4];
        float4 w0 = *(const float4*)&ws[(k4 * 4 + 0) * H + c];
        acc.x = fmaf(a.x, w0.x, acc.x); acc.y = fmaf(a.x, w0.y, acc.y);
        acc.z = fmaf(a.x, w0.z, acc.z); acc.w = fmaf(a.x, w0.w, acc.w);
        float4 w1 = *(const float4*)&ws[(k4 * 4 + 1) * H + c];
        acc.x = fmaf(a.y, w1.x, acc.x); acc.y = fmaf(a.y, w1.y, acc.y);
        acc.z = fmaf(a.y, w1.z, acc.z); acc.w = fmaf(a.y, w1.w, acc.w);
        float4 w2 = *(const float4*)&ws[(k4 * 4 + 2) * H + c];
        acc.x = fmaf(a.z, w2.x, acc.x); acc.y = fmaf(a.z, w2.y, acc.y);
        acc.z = fmaf(a.z, w2.z, acc.z); acc.w = fmaf(a.z, w2.w, acc.w);
        float4 w3 = *(const float4*)&ws[(k4 * 4 + 3) * H + c];
        acc.x = fmaf(a.w, w3.x, acc.x); acc.y = fmaf(a.w, w3.y, acc.y);
        acc.z = fmaf(a.w, w3.z, acc.z); acc.w = fmaf(a.w, w3.w, acc.w);
    }
    float4 We0 = *(const float4*)&cw[64 * H + c];
    float4 We1 = *(const float4*)&cw[65 * H + c];
    float S1 = rsum16(acc.x + acc.y + acc.z + acc.w);
    float S2 = rsum16(acc.x * acc.x + acc.y * acc.y + acc.z * acc.z + acc.w * acc.w);
    float D0 = rsum16(acc.x * We0.x + acc.y * We0.y + acc.z * We0.z + acc.w * We0.w);
    float D1 = rsum16(acc.x * We1.x + acc.y * We1.y + acc.z * We1.z + acc.w * We1.w);
    if (valid) {
        *(float4*)&g_hW[node * H + c] = acc;
        if (hl == 0) g_stats[node] = make_float4(S1, S2, D0, D1);
    }
}

// ---------------- per-layer: aggregate + residual/LN update ----------------
// Warp per dst node. Prologue: 32 lanes compute 32 edges' LN scalars into smem.
// Sweep: 2 edges/iteration (half-warp each, lane owns 4 channels, LDG.128 gather).
__global__ __launch_bounds__(256) void conv_agg_kernel(
    const float* __restrict__ cw,
    const float* __restrict__ mg, const float* __restrict__ mb,
    const float* __restrict__ ng, const float* __restrict__ nb,
    const float* __restrict__ og, const float* __restrict__ ob,
    const int* __restrict__ batch, int do_pool, int N)
{
    __shared__ float4 s_meta[8][32];  // (ex, ey, mu, r) per edge
    __shared__ int    s_src[8][32];   // src*H row offset
    int t = threadIdx.x;
    int wid = t >> 5, lane = t & 31, half = lane >> 4, hl = lane & 15;
    int node = blockIdx.x * 8 + wid;
    if (node >= N) return;
    int c = hl * 4;
    float4 We0 = *(const float4*)&cw[64 * H + c];
    float4 We1 = *(const float4*)&cw[65 * H + c];
    float4 mgv = *(const float4*)&mg[c];
    float4 mbv = *(const float4*)&mb[c];
    float SW0 = g_lc[0], SW1 = g_lc[1], Q0 = g_lc[2], Q1 = g_lc[3], D01 = g_lc[4];
    int beg = g_off[node], end = g_off[node + 1];
    float4 acc = make_float4(0.f, 0.f, 0.f, 0.f);
    for (int base = beg; base < end; base += 32) {
        int cnt = min(32, end - base);
        float4 md = make_float4(0.f, 0.f, 0.f, 1.f);
        int s_off = 0;
        if (lane < cnt) {
            int s = g_csr_src[base + lane];
            float2 ea = g_csr_ea[base + lane];
            float4 st = g_stats[s];
            float sum = st.x + ea.x * SW0 + ea.y * SW1;
            float ssq = st.y + ea.x * ea.x * Q0 + ea.y * ea.y * Q1
                      + 2.0f * (ea.x * st.z + ea.y * st.w + ea.x * ea.y * D01);
            float mu = sum * (1.0f / H);
            float var = ssq * (1.0f / H) - mu * mu;
            md = make_float4(ea.x, ea.y, mu, rsqrtf(var + 1e-5f));
            s_off = s * H;
        }
        s_meta[wid][lane] = md;
        s_src[wid][lane] = s_off;
        __syncwarp();
        for (int j2 = 0; j2 < cnt; j2 += 2) {
            int j = j2 + half;                // j <= 31 always
            float4 m = s_meta[wid][j];
            int so = s_src[wid][j];
            bool act = j < cnt;
            float4 hv = *(const float4*)&g_hW[so + c];
            float A0 = m.w * mgv.x, A1 = m.w * mgv.y, A2 = m.w * mgv.z, A3 = m.w * mgv.w;
            float e0 = fmaf(m.x, We0.x, fmaf(m.y, We1.x, -m.z));
            float e1 = fmaf(m.x, We0.y, fmaf(m.y, We1.y, -m.z));
            float e2 = fmaf(m.x, We0.z, fmaf(m.y, We1.z, -m.z));
            float e3 = fmaf(m.x, We0.w, fmaf(m.y, We1.w, -m.z));
            float v0 = gelu_fast(fmaf(hv.x, A0, fmaf(e0, A0, mbv.x)));
            float v1 = gelu_fast(fmaf(hv.y, A1, fmaf(e1, A1, mbv.y)));
            float v2 = gelu_fast(fmaf(hv.z, A2, fmaf(e2, A2, mbv.z)));
            float v3 = gelu_fast(fmaf(hv.w, A3, fmaf(e3, A3, mbv.w)));
            if (act) { acc.x += v0; acc.y += v1; acc.z += v2; acc.w += v3; }
        }
        __syncwarp();
    }
    // merge the two halves (channels identical across halves afterwards)
    acc.x += __shfl_xor_sync(0xffffffffu, acc.x, 16);
    acc.y += __shfl_xor_sync(0xffffffffu, acc.y, 16);
    acc.z += __shfl_xor_sync(0xffffffffu, acc.z, 16);
    acc.w += __shfl_xor_sync(0xffffffffu, acc.w, 16);

    float inv = 1.0f / fmaxf((float)(end - beg), 1.0f);
    float4 hrow = *(const float4*)&g_h[node * H + c];
    float t0 = acc.x * inv + hrow.x;
    float t1 = acc.y * inv + hrow.y;
    float t2 = acc.z * inv + hrow.z;
    float t3 = acc.w * inv + hrow.w;
    float s1 = rsum16(t0 + t1 + t2 + t3);
    float s2 = rsum16(t0 * t0 + t1 * t1 + t2 * t2 + t3 * t3);
    float mu = s1 * (1.0f / H);
    float r  = rsqrtf(s2 * (1.0f / H) - mu * mu + 1e-5f);
    float4 ngv = *(const float4*)&ng[c];
    float4 nbv = *(const float4*)&nb[c];
    float co0 = (t0 - mu) * r * ngv.x + nbv.x;
    float co1 = (t1 - mu) * r * ngv.y + nbv.y;
    float co2 = (t2 - mu) * r * ngv.z + nbv.z;
    float co3 = (t3 - mu) * r * ngv.w + nbv.w;
    s1 = rsum16(co0 + co1 + co2 + co3);
    s2 = rsum16(co0 * co0 + co1 * co1 + co2 * co2 + co3 * co3);
    mu = s1 * (1.0f / H);
    r  = rsqrtf(s2 * (1.0f / H) - mu * mu + 1e-5f);
    float4 ogv = *(const float4*)&og[c];
    float4 obv = *(const float4*)&ob[c];
    float nh0 = hrow.x + (co0 - mu) * r * ogv.x + obv.x;
    float nh1 = hrow.y + (co1 - mu) * r * ogv.y + obv.y;
    float nh2 = hrow.z + (co2 - mu) * r * ogv.z + obv.z;
    float nh3 = hrow.w + (co3 - mu) * r * ogv.w + obv.w;
    if (!do_pool) {
        if (half == 0) *(float4*)&g_h[node * H + c] = make_float4(nh0, nh1, nh2, nh3);
    } else {
        int b = batch[node];
        if (half == 0) {
            atomicAdd(&g_pool[b * H + c + 0], nh0);
            atomicAdd(&g_pool[b * H + c + 1], nh1);
            atomicAdd(&g_pool[b * H + c + 2], nh2);
            atomicAdd(&g_pool[b * H + c + 3], nh3);
        }
        if (lane == 0) atomicAdd(&g_cnt[b], 1);
    }
}

// ---------------- head MLP (warp per graph) ----------------
__global__ __launch_bounds__(256) void head_kernel(
    const float* __restrict__ w1, const float* __restrict__ b1,
    const float* __restrict__ gg1, const float* __restrict__ bb1,
    const float* __restrict__ w2, const float* __restrict__ b2,
    const float* __restrict__ gg2, const float* __restrict__ bb2,
    const float* __restrict__ w3, const float* __restrict__ b3,
    float* __restrict__ out, int B)
{
    int t = threadIdx.x;
    int g = blockIdx.x * 8 + (t >> 5);
    int lane = t & 31;
    if (g >= B) return;
    float inv = 1.0f / fmaxf((float)g_cnt[g], 1.0f);
    int c0 = 2 * lane, c1 = c0 + 1;
    float v0 = g_pool[g * H + c0] * inv;
    float v1 = g_pool[g * H + c1] * inv;
    float acc0 = b1[c0], acc1 = b1[c1];
    #pragma unroll
    for (int k = 0; k < 32; k++) {
        float a = __shfl_sync(0xffffffffu, v0, k);
        float b_ = __shfl_sync(0xffffffffu, v1, k);
        acc0 = fmaf(a, w1[(2 * k) * H + c0], acc0); acc0 = fmaf(b_, w1[(2 * k + 1) * H + c0], acc0);
        acc1 = fmaf(a, w1[(2 * k) * H + c1], acc1); acc1 = fmaf(b_, w1[(2 * k + 1) * H + c1], acc1);
    }
    float s1 = warp_sum(acc0 + acc1);
    float s2 = warp_sum(acc0 * acc0 + acc1 * acc1);
    float mu = s1 * (1.0f / H);
    float r  = rsqrtf(s2 * (1.0f / H) - mu * mu + 1e-5f);
    float a0 = fmaxf((acc0 - mu) * r * gg1[c0] + bb1[c0], 0.0f);
    float a1 = fmaxf((acc1 - mu) * r * gg1[c1] + bb1[c1], 0.0f);
    float acc = b2[lane];
    #pragma unroll
    for (int k = 0; k < 32; k++) {
        float a = __shfl_sync(0xffffffffu, a0, k);
        float bb = __shfl_sync(0xffffffffu, a1, k);
        acc = fmaf(a, w2[(2 * k) * 32 + lane], acc);
        acc = fmaf(bb, w2[(2 * k + 1) * 32 + lane], acc);
    }
    s1 = warp_sum(acc);
    s2 = warp_sum(acc * acc);
    mu = s1 * (1.0f / 32.0f);
    r  = rsqrtf(s2 * (1.0f / 32.0f) - mu * mu + 1e-5f);
    float z = fmaxf((acc - mu) * r * gg2[lane] + bb2[lane], 0.0f);
    float o = warp_sum(z * w3[lane]);
    if (lane == 0) out[g] = o + b3[0];
}

// ---------------- launch ----------------
extern "C" void kernel_launch(void* const* d_in, const int* in_sizes, int n_in,
                              void* d_out, int out_size)
{
    const float* x        = (const float*)d_in[0];
    const float* edge_attr= (const float*)d_in[1];
    const float* ne_w1 = (const float*)d_in[2];
    const float* ne_b1 = (const float*)d_in[3];
    const float* ne_g1 = (const float*)d_in[4];
    const float* ne_be1= (const float*)d_in[5];
    const float* ne_w2 = (const float*)d_in[6];
    const float* ne_b2 = (const float*)d_in[7];
    const float* ne_g2 = (const float*)d_in[8];
    const float* ne_be2= (const float*)d_in[9];
    const float* conv_w = (const float*)d_in[10];
    const float* conv_b = (const float*)d_in[11];
    const float* conv_mg= (const float*)d_in[12];
    const float* conv_mb= (const float*)d_in[13];
    const float* conv_ng= (const float*)d_in[14];
    const float* conv_nb= (const float*)d_in[15];
    const float* out_ng = (const float*)d_in[16];
    const float* out_nb = (const float*)d_in[17];
    const float* m_w1 = (const float*)d_in[18];
    const float* m_b1 = (const float*)d_in[19];
    const float* m_g1 = (const float*)d_in[20];
    const float* m_be1= (const float*)d_in[21];
    const float* m_w2 = (const float*)d_in[22];
    const float* m_b2 = (const float*)d_in[23];
    const float* m_g2 = (const float*)d_in[24];
    const float* m_be2= (const float*)d_in[25];
    const float* m_w3 = (const float*)d_in[26];
    const float* m_b3 = (const float*)d_in[27];
    const int* edge_index = (const int*)d_in[28];
    const int* batch      = (const int*)d_in[29];

    int N = in_sizes[0] / 2;
    int E = in_sizes[1] / 2;
    int B = out_size;

    int NB8  = (N + 7) / 8;
    int NB16 = (N + 15) / 16;
    int EB   = (E + 255) / 256;
    int nscan = (N + 511) / 512;

    zero_kernel<<<(N + 255) / 256, 256>>>(N, B);
    node_embed_kernel<<<NB8, 256>>>(x, ne_w1, ne_b1, ne_g1, ne_be1,
                                    ne_w2, ne_b2, ne_g2, ne_be2, N);
    count_deg_kernel<<<EB, 256>>>(edge_index, E);
    scan_local_kernel<<<nscan, 512>>>(N);
    scan_bsum_kernel<<<1, 256>>>(nscan);
    scan_add_kernel<<<nscan, 512>>>(N, E);
    fill_csr_kernel<<<EB, 256>>>(edge_index, edge_attr, E);

    for (int l = 0; l < 3; l++) {
        const float* cw = conv_w + l * (H + 2) * H;
        prep_layer_kernel<<<1, 32>>>(cw);
        hw_stats_kernel<<<NB16, 256>>>(cw, conv_b + l * H, N);
        conv_agg_kernel<<<NB8, 256>>>(cw,
            conv_mg + l * H, conv_mb + l * H,
            conv_ng + l * H, conv_nb + l * H,
            out_ng + l * H, out_nb + l * H,
            batch, (l == 2) ? 1 : 0, N);
    }

    head_kernel<<<(B + 7) / 8, 256>>>(m_w1, m_b1, m_g1, m_be1,
                                      m_w2, m_b2, m_g2, m_be2,
                                      m_w3, m_b3, (float*)d_out, B);
}

// round 5
// speedup vs baseline: 1.0201x; 1.0201x over previous
#include <cuda_runtime.h>
#include <math.h>

#define MAXN 100000
#define MAXE 1600000
#define MAXB 256
#define H 64

// ---------------- scratch (static device globals; no allocation) ----------------
__device__ float  g_h[MAXN * H];            // node features
__device__ float  g_hW[2][MAXN * H];        // ping-pong: h @ conv_w[l][:64] + b
__device__ float4 g_stats[2][MAXN];         // ping-pong LN stats of hW row
__device__ int    g_deg[MAXN];
__device__ int    g_off[MAXN + 1];
__device__ int    g_cur[MAXN];
__device__ int    g_csr_src[MAXE];
__device__ float2 g_csr_ea[MAXE];
__device__ int    g_bsum[512];
__device__ float  g_lc[3][8];               // per-layer constants
__device__ float  g_pool[MAXB * H];
__device__ int    g_cnt[MAXB];

__device__ __forceinline__ float warp_sum(float v) {
    #pragma unroll
    for (int o = 16; o > 0; o >>= 1) v += __shfl_xor_sync(0xffffffffu, v, o);
    return v;
}
__device__ __forceinline__ float gelu_exact(float v) {
    return 0.5f * v * (1.0f + erff(v * 0.7071067811865476f));
}
// fast gelu via HW tanh (MUFU.TANH); |err| vs exact erf-gelu ~3e-4 abs
__device__ __forceinline__ float gelu_fast(float x) {
    float x2 = x * x;
    float inner = fmaf(0.0356774081f, x2, 0.7978845608f);
    float u = x * inner;
    float t;
    asm("tanh.approx.f32 %0, %1;" : "=f"(t) : "f"(u));
    float hx = 0.5f * x;
    return fmaf(hx, t, hx);
}

// ---------------- zero init + all-layer edge-weight constants ----------------
__global__ void zero_prep_kernel(const float* __restrict__ conv_w, int N, int B) {
    int i = blockIdx.x * blockDim.x + threadIdx.x;
    if (i < N) { g_deg[i] = 0; g_cur[i] = 0; }
    if (i < B * H) g_pool[i] = 0.0f;
    if (i < B) g_cnt[i] = 0;
    if (blockIdx.x == 0 && threadIdx.x < 96) {
        int w = threadIdx.x >> 5, lane = threadIdx.x & 31;
        const float* cw = conv_w + w * (H + 2) * H;
        float a0 = cw[64 * H + 2 * lane], a1 = cw[64 * H + 2 * lane + 1];
        float b0 = cw[65 * H + 2 * lane], b1 = cw[65 * H + 2 * lane + 1];
        float SW0 = warp_sum(a0 + a1);
        float SW1 = warp_sum(b0 + b1);
        float Q0  = warp_sum(a0 * a0 + a1 * a1);
        float Q1  = warp_sum(b0 * b0 + b1 * b1);
        float D01 = warp_sum(a0 * b0 + a1 * b1);
        if (lane == 0) {
            g_lc[w][0] = SW0; g_lc[w][1] = SW1; g_lc[w][2] = Q0;
            g_lc[w][3] = Q1;  g_lc[w][4] = D01;
        }
    }
}

// ---------------- node embedding MLP + fused hW0/stats0 (warp per node) ------
__global__ __launch_bounds__(256) void node_embed_kernel(
    const float* __restrict__ x,
    const float* __restrict__ w1, const float* __restrict__ b1,
    const float* __restrict__ g1, const float* __restrict__ be1,
    const float* __restrict__ w2, const float* __restrict__ b2,
    const float* __restrict__ g2, const float* __restrict__ be2,
    const float* __restrict__ cw0, const float* __restrict__ cb0, int N)
{
    __shared__ float ws[H * H];
    __shared__ float ws0[H * H];
    int t = threadIdx.x;
    for (int i = t; i < H * H; i += 256) { ws[i] = w2[i]; ws0[i] = cw0[i]; }
    __syncthreads();
    int node = blockIdx.x * 8 + (t >> 5);
    int lane = t & 31;
    if (node >= N) return;
    int c0 = 2 * lane, c1 = c0 + 1;
    float x0 = x[node * 2], x1 = x[node * 2 + 1];
    float p0 = fmaf(x1, w1[H + c0], fmaf(x0, w1[c0], b1[c0]));
    float p1 = fmaf(x1, w1[H + c1], fmaf(x0, w1[c1], b1[c1]));
    float s = warp_sum(p0 + p1);
    float q = warp_sum(p0 * p0 + p1 * p1);
    float mu = s * (1.0f / H);
    float r  = rsqrtf(q * (1.0f / H) - mu * mu + 1e-5f);
    float a0 = gelu_exact((p0 - mu) * r * g1[c0] + be1[c0]);
    float a1 = gelu_exact((p1 - mu) * r * g1[c1] + be1[c1]);
    float acc0 = b2[c0], acc1 = b2[c1];
    #pragma unroll
    for (int k = 0; k < 32; k++) {
        float u = __shfl_sync(0xffffffffu, a0, k);
        float v = __shfl_sync(0xffffffffu, a1, k);
        const float* r0 = &ws[(2 * k) * H];
        const float* r1 = &ws[(2 * k + 1) * H];
        acc0 = fmaf(u, r0[c0], acc0); acc0 = fmaf(v, r1[c0], acc0);
        acc1 = fmaf(u, r0[c1], acc1); acc1 = fmaf(v, r1[c1], acc1);
    }
    s = warp_sum(acc0 + acc1);
    q = warp_sum(acc0 * acc0 + acc1 * acc1);
    mu = s * (1.0f / H);
    r  = rsqrtf(q * (1.0f / H) - mu * mu + 1e-5f);
    float f0 = gelu_exact((acc0 - mu) * r * g2[c0] + be2[c0]);
    float f1 = gelu_exact((acc1 - mu) * r * g2[c1] + be2[c1]);
    *(float2*)&g_h[node * H + c0] = make_float2(f0, f1);
    // fused hW0 + stats0 (buffer 0)
    float hw0 = cb0[c0], hw1 = cb0[c1];
    #pragma unroll
    for (int k = 0; k < 32; k++) {
        float u = __shfl_sync(0xffffffffu, f0, k);
        float v = __shfl_sync(0xffffffffu, f1, k);
        const float* r0 = &ws0[(2 * k) * H];
        const float* r1 = &ws0[(2 * k + 1) * H];
        hw0 = fmaf(u, r0[c0], hw0); hw0 = fmaf(v, r1[c0], hw0);
        hw1 = fmaf(u, r0[c1], hw1); hw1 = fmaf(v, r1[c1], hw1);
    }
    *(float2*)&g_hW[0][node * H + c0] = make_float2(hw0, hw1);
    float w00 = cw0[64 * H + c0], w01 = cw0[64 * H + c1];
    float w10 = cw0[65 * H + c0], w11 = cw0[65 * H + c1];
    float S1 = warp_sum(hw0 + hw1);
    float S2 = warp_sum(hw0 * hw0 + hw1 * hw1);
    float D0 = warp_sum(hw0 * w00 + hw1 * w01);
    float D1 = warp_sum(hw0 * w10 + hw1 * w11);
    if (lane == 0) g_stats[0][node] = make_float4(S1, S2, D0, D1);
}

// ---------------- CSR build ----------------
__global__ void count_deg_kernel(const int* __restrict__ ei, int E) {
    int e = blockIdx.x * blockDim.x + threadIdx.x;
    if (e < E) atomicAdd(&g_deg[ei[E + e]], 1);
}

__global__ void scan_local_kernel(int N) {
    __shared__ int wsums[16];
    int t = threadIdx.x, lane = t & 31, w = t >> 5;
    int i = blockIdx.x * 512 + t;
    int x = (i < N) ? g_deg[i] : 0;
    int v = x;
    #pragma unroll
    for (int o = 1; o < 32; o <<= 1) { int n = __shfl_up_sync(0xffffffffu, v, o); if (lane >= o) v += n; }
    if (lane == 31) wsums[w] = v;
    __syncthreads();
    if (w == 0) {
        int s = (lane < 16) ? wsums[lane] : 0;
        #pragma unroll
        for (int o = 1; o < 16; o <<= 1) { int n = __shfl_up_sync(0xffffffffu, s, o); if (lane >= o) s += n; }
        if (lane < 16) wsums[lane] = s;
    }
    __syncthreads();
    int off = (w > 0) ? wsums[w - 1] : 0;
    int incl = v + off;
    if (i < N) g_off[i] = incl - x;
    if (t == 511) g_bsum[blockIdx.x] = incl;
}

__global__ void scan_bsum_kernel(int nblk) {
    __shared__ int wsums[8];
    int t = threadIdx.x, lane = t & 31, w = t >> 5;
    int x = (t < nblk) ? g_bsum[t] : 0;
    int v = x;
    #pragma unroll
    for (int o = 1; o < 32; o <<= 1) { int n = __shfl_up_sync(0xffffffffu, v, o); if (lane >= o) v += n; }
    if (lane == 31) wsums[w] = v;
    __syncthreads();
    if (w == 0) {
        int s = (lane < 8) ? wsums[lane] : 0;
        #pragma unroll
        for (int o = 1; o < 8; o <<= 1) { int n = __shfl_up_sync(0xffffffffu, s, o); if (lane >= o && lane < 8) s += n; }
        if (lane < 8) wsums[lane] = s;
    }
    __syncthreads();
    int off = (w > 0) ? wsums[w - 1] : 0;
    if (t < nblk) g_bsum[t] = v + off - x;   // exclusive
}

__global__ void scan_add_kernel(int N, int E) {
    int i = blockIdx.x * 512 + threadIdx.x;
    if (i < N) g_off[i] += g_bsum[blockIdx.x];
    if (i == 0) g_off[N] = E;
}

__global__ void fill_csr_kernel(const int* __restrict__ ei, const float* __restrict__ ea, int E) {
    int e = blockIdx.x * blockDim.x + threadIdx.x;
    if (e >= E) return;
    int d = ei[E + e];
    int p = g_off[d] + atomicAdd(&g_cur[d], 1);
    g_csr_src[p] = ei[e];
    g_csr_ea[p] = *(const float2*)&ea[2 * e];
}

// ---------------- per-layer: aggregate + residual/LN update (warp per dst) ----------------
// Round-2 sweep (lane = 2 channels, shfl-broadcast edge scalars). Epilogue fuses the
// next layer's hW/stats GEMM (weights in smem) or the global mean pool (last layer).
__global__ __launch_bounds__(256) void conv_agg_kernel(
    const float* __restrict__ cw,
    const float* __restrict__ mg, const float* __restrict__ mb,
    const float* __restrict__ ng, const float* __restrict__ nb,
    const float* __restrict__ og, const float* __restrict__ ob,
    const float* __restrict__ cwn, const float* __restrict__ cbn,
    const int* __restrict__ batch, int l, int do_pool, int N)
{
    __shared__ float wsn[H * H];
    int t = threadIdx.x;
    if (!do_pool) {
        for (int i = t; i < H * H; i += 256) wsn[i] = cwn[i];
    }
    __syncthreads();
    int node = blockIdx.x * 8 + (t >> 5);
    int lane = t & 31;
    if (node >= N) return;
    int rb = l & 1, wb = rb ^ 1;
    int c0 = 2 * lane, c1 = c0 + 1;
    float We00 = cw[64 * H + c0], We01 = cw[64 * H + c1];
    float We10 = cw[65 * H + c0], We11 = cw[65 * H + c1];
    float mg0 = mg[c0], mg1 = mg[c1], mb0 = mb[c0], mb1 = mb[c1];
    float SW0 = g_lc[l][0], SW1 = g_lc[l][1], Q0 = g_lc[l][2], Q1 = g_lc[l][3], D01 = g_lc[l][4];
    int beg = g_off[node], end = g_off[node + 1];
    float acc0 = 0.0f, acc1 = 0.0f;
    const float* hWb = g_hW[rb];
    for (int base = beg; base < end; base += 32) {
        int cnt = min(32, end - base);
        int   s_l = 0;
        float eax_l = 0.0f, eay_l = 0.0f, mu_l = 0.0f, r_l = 0.0f;
        if (lane < cnt) {
            s_l = g_csr_src[base + lane];
            float2 ea = g_csr_ea[base + lane];
            float4 st = g_stats[rb][s_l];
            float sum = st.x + ea.x * SW0 + ea.y * SW1;
            float ssq = st.y + ea.x * ea.x * Q0 + ea.y * ea.y * Q1
                      + 2.0f * (ea.x * st.z + ea.y * st.w + ea.x * ea.y * D01);
            mu_l = sum * (1.0f / H);
            float var = ssq * (1.0f / H) - mu_l * mu_l;
            r_l = rsqrtf(var + 1e-5f);
            eax_l = ea.x; eay_l = ea.y;
        }
        #pragma unroll 4
        for (int j = 0; j < cnt; j++) {
            int   ss = __shfl_sync(0xffffffffu, s_l, j);
            float ex = __shfl_sync(0xffffffffu, eax_l, j);
            float ey = __shfl_sync(0xffffffffu, eay_l, j);
            float m  = __shfl_sync(0xffffffffu, mu_l, j);
            float rj = __shfl_sync(0xffffffffu, r_l, j);
            float2 hv = *(const float2*)&hWb[ss * H + c0];
            float A0 = rj * mg0, A1 = rj * mg1;
            float e0 = fmaf(ey, We10, ex * We00) - m;
            float e1 = fmaf(ey, We11, ex * We01) - m;
            float K0 = fmaf(e0, A0, mb0);
            float K1 = fmaf(e1, A1, mb1);
            acc0 += gelu_fast(fmaf(hv.x, A0, K0));
            acc1 += gelu_fast(fmaf(hv.y, A1, K1));
        }
    }
    float inv = 1.0f / fmaxf((float)(end - beg), 1.0f);
    float2 hrow = *(const float2*)&g_h[node * H + c0];
    float t0 = acc0 * inv + hrow.x;
    float t1 = acc1 * inv + hrow.y;
    float s1 = warp_sum(t0 + t1);
    float s2 = warp_sum(t0 * t0 + t1 * t1);
    float mu = s1 * (1.0f / H);
    float r  = rsqrtf(s2 * (1.0f / H) - mu * mu + 1e-5f);
    float co0 = (t0 - mu) * r * ng[c0] + nb[c0];
    float co1 = (t1 - mu) * r * ng[c1] + nb[c1];
    s1 = warp_sum(co0 + co1);
    s2 = warp_sum(co0 * co0 + co1 * co1);
    mu = s1 * (1.0f / H);
    r  = rsqrtf(s2 * (1.0f / H) - mu * mu + 1e-5f);
    float u0 = (co0 - mu) * r * og[c0] + ob[c0];
    float u1 = (co1 - mu) * r * og[c1] + ob[c1];
    float nh0 = hrow.x + u0, nh1 = hrow.y + u1;
    if (do_pool) {
        int b = batch[node];
        atomicAdd(&g_pool[b * H + c0], nh0);
        atomicAdd(&g_pool[b * H + c1], nh1);
        if (lane == 0) atomicAdd(&g_cnt[b], 1);
        return;
    }
    *(float2*)&g_h[node * H + c0] = make_float2(nh0, nh1);
    // fused next-layer hW + stats into buffer wb
    float hw0 = cbn[c0], hw1 = cbn[c1];
    #pragma unroll
    for (int k = 0; k < 32; k++) {
        float u = __shfl_sync(0xffffffffu, nh0, k);
        float v = __shfl_sync(0xffffffffu, nh1, k);
        const float* r0 = &wsn[(2 * k) * H];
        const float* r1 = &wsn[(2 * k + 1) * H];
        hw0 = fmaf(u, r0[c0], hw0); hw0 = fmaf(v, r1[c0], hw0);
        hw1 = fmaf(u, r0[c1], hw1); hw1 = fmaf(v, r1[c1], hw1);
    }
    *(float2*)&g_hW[wb][node * H + c0] = make_float2(hw0, hw1);
    float w00 = cwn[64 * H + c0], w01 = cwn[64 * H + c1];
    float w10 = cwn[65 * H + c0], w11 = cwn[65 * H + c1];
    float S1 = warp_sum(hw0 + hw1);
    float S2 = warp_sum(hw0 * hw0 + hw1 * hw1);
    float D0 = warp_sum(hw0 * w00 + hw1 * w01);
    float D1 = warp_sum(hw0 * w10 + hw1 * w11);
    if (lane == 0) g_stats[wb][node] = make_float4(S1, S2, D0, D1);
}

// ---------------- head MLP (warp per graph) ----------------
__global__ __launch_bounds__(256) void head_kernel(
    const float* __restrict__ w1, const float* __restrict__ b1,
    const float* __restrict__ gg1, const float* __restrict__ bb1,
    const float* __restrict__ w2, const float* __restrict__ b2,
    const float* __restrict__ gg2, const float* __restrict__ bb2,
    const float* __restrict__ w3, const float* __restrict__ b3,
    float* __restrict__ out, int B)
{
    int t = threadIdx.x;
    int g = blockIdx.x * 8 + (t >> 5);
    int lane = t & 31;
    if (g >= B) return;
    float inv = 1.0f / fmaxf((float)g_cnt[g], 1.0f);
    int c0 = 2 * lane, c1 = c0 + 1;
    float v0 = g_pool[g * H + c0] * inv;
    float v1 = g_pool[g * H + c1] * inv;
    float acc0 = b1[c0], acc1 = b1[c1];
    #pragma unroll
    for (int k = 0; k < 32; k++) {
        float a = __shfl_sync(0xffffffffu, v0, k);
        float b_ = __shfl_sync(0xffffffffu, v1, k);
        acc0 = fmaf(a, w1[(2 * k) * H + c0], acc0); acc0 = fmaf(b_, w1[(2 * k + 1) * H + c0], acc0);
        acc1 = fmaf(a, w1[(2 * k) * H + c1], acc1); acc1 = fmaf(b_, w1[(2 * k + 1) * H + c1], acc1);
    }
    float s1 = warp_sum(acc0 + acc1);
    float s2 = warp_sum(acc0 * acc0 + acc1 * acc1);
    float mu = s1 * (1.0f / H);
    float r  = rsqrtf(s2 * (1.0f / H) - mu * mu + 1e-5f);
    float a0 = fmaxf((acc0 - mu) * r * gg1[c0] + bb1[c0], 0.0f);
    float a1 = fmaxf((acc1 - mu) * r * gg1[c1] + bb1[c1], 0.0f);
    float acc = b2[lane];
    #pragma unroll
    for (int k = 0; k < 32; k++) {
        float a = __shfl_sync(0xffffffffu, a0, k);
        float bb = __shfl_sync(0xffffffffu, a1, k);
        acc = fmaf(a, w2[(2 * k) * 32 + lane], acc);
        acc = fmaf(bb, w2[(2 * k + 1) * 32 + lane], acc);
    }
    s1 = warp_sum(acc);
    s2 = warp_sum(acc * acc);
    mu = s1 * (1.0f / 32.0f);
    r  = rsqrtf(s2 * (1.0f / 32.0f) - mu * mu + 1e-5f);
    float z = fmaxf((acc - mu) * r * gg2[lane] + bb2[lane], 0.0f);
    float o = warp_sum(z * w3[lane]);
    if (lane == 0) out[g] = o + b3[0];
}

// ---------------- launch ----------------
extern "C" void kernel_launch(void* const* d_in, const int* in_sizes, int n_in,
                              void* d_out, int out_size)
{
    const float* x        = (const float*)d_in[0];
    const float* edge_attr= (const float*)d_in[1];
    const float* ne_w1 = (const float*)d_in[2];
    const float* ne_b1 = (const float*)d_in[3];
    const float* ne_g1 = (const float*)d_in[4];
    const float* ne_be1= (const float*)d_in[5];
    const float* ne_w2 = (const float*)d_in[6];
    const float* ne_b2 = (const float*)d_in[7];
    const float* ne_g2 = (const float*)d_in[8];
    const float* ne_be2= (const float*)d_in[9];
    const float* conv_w = (const float*)d_in[10];
    const float* conv_b = (const float*)d_in[11];
    const float* conv_mg= (const float*)d_in[12];
    const float* conv_mb= (const float*)d_in[13];
    const float* conv_ng= (const float*)d_in[14];
    const float* conv_nb= (const float*)d_in[15];
    const float* out_ng = (const float*)d_in[16];
    const float* out_nb = (const float*)d_in[17];
    const float* m_w1 = (const float*)d_in[18];
    const float* m_b1 = (const float*)d_in[19];
    const float* m_g1 = (const float*)d_in[20];
    const float* m_be1= (const float*)d_in[21];
    const float* m_w2 = (const float*)d_in[22];
    const float* m_b2 = (const float*)d_in[23];
    const float* m_g2 = (const float*)d_in[24];
    const float* m_be2= (const float*)d_in[25];
    const float* m_w3 = (const float*)d_in[26];
    const float* m_b3 = (const float*)d_in[27];
    const int* edge_index = (const int*)d_in[28];
    const int* batch      = (const int*)d_in[29];

    int N = in_sizes[0] / 2;
    int E = in_sizes[1] / 2;
    int B = out_size;

    int NB8  = (N + 7) / 8;
    int EB   = (E + 255) / 256;
    int nscan = (N + 511) / 512;

    zero_prep_kernel<<<(N + 255) / 256, 256>>>(conv_w, N, B);
    node_embed_kernel<<<NB8, 256>>>(x, ne_w1, ne_b1, ne_g1, ne_be1,
                                    ne_w2, ne_b2, ne_g2, ne_be2,
                                    conv_w, conv_b, N);
    count_deg_kernel<<<EB, 256>>>(edge_index, E);
    scan_local_kernel<<<nscan, 512>>>(N);
    scan_bsum_kernel<<<1, 256>>>(nscan);
    scan_add_kernel<<<nscan, 512>>>(N, E);
    fill_csr_kernel<<<EB, 256>>>(edge_index, edge_attr, E);

    for (int l = 0; l < 3; l++) {
        const float* cw  = conv_w + l * (H + 2) * H;
        const float* cwn = conv_w + ((l + 1) % 3) * (H + 2) * H;
        const float* cbn = conv_b + ((l + 1) % 3) * H;
        conv_agg_kernel<<<NB8, 256>>>(cw,
            conv_mg + l * H, conv_mb + l * H,
            conv_ng + l * H, conv_nb + l * H,
            out_ng + l * H, out_nb + l * H,
            cwn, cbn, batch, l, (l == 2) ? 1 : 0, N);
    }

    head_kernel<<<(B + 7) / 8, 256>>>(m_w1, m_b1, m_g1, m_be1,
                                      m_w2, m_b2, m_g2, m_be2,
                                      m_w3, m_b3, (float*)d_out, B);
}

// round 6
// speedup vs baseline: 1.0233x; 1.0032x over previous
#include <cuda_runtime.h>
#include <math.h>

#define MAXN 100000
#define MAXE 1600000
#define MAXB 256
#define H 64

typedef unsigned long long ull;

// ---------------- scratch (static device globals; no allocation) ----------------
__device__ float  g_h[MAXN * H];            // node features
__device__ float  g_hW[2][MAXN * H];        // ping-pong: h @ conv_w[l][:64] + b
__device__ float4 g_stats[2][MAXN];         // ping-pong LN stats of hW row
__device__ int    g_deg[MAXN];
__device__ int    g_off[MAXN + 1];
__device__ int    g_cur[MAXN];
__device__ int    g_csr_src[MAXE];
__device__ float2 g_csr_ea[MAXE];
__device__ int    g_bsum[512];
__device__ float  g_lc[3][8];               // per-layer constants
__device__ float  g_pool[MAXB * H];
__device__ int    g_cnt[MAXB];

// ---------------- f32x2 packed helpers (sm_100+) ----------------
__device__ __forceinline__ ull pk(float lo, float hi) {
    ull r; asm("mov.b64 %0, {%1, %2};" : "=l"(r) : "f"(lo), "f"(hi)); return r;
}
__device__ __forceinline__ ull pk1(float v) { return pk(v, v); }
__device__ __forceinline__ void upk(ull p, float& lo, float& hi) {
    asm("mov.b64 {%0, %1}, %2;" : "=f"(lo), "=f"(hi) : "l"(p));
}
__device__ __forceinline__ ull fma2(ull a, ull b, ull c) {
    ull d; asm("fma.rn.f32x2 %0, %1, %2, %3;" : "=l"(d) : "l"(a), "l"(b), "l"(c)); return d;
}
__device__ __forceinline__ ull mul2(ull a, ull b) {
    ull d; asm("mul.rn.f32x2 %0, %1, %2;" : "=l"(d) : "l"(a), "l"(b)); return d;
}
__device__ __forceinline__ ull add2(ull a, ull b) {
    ull d; asm("add.rn.f32x2 %0, %1, %2;" : "=l"(d) : "l"(a), "l"(b)); return d;
}

__device__ __forceinline__ float warp_sum(float v) {
    #pragma unroll
    for (int o = 16; o > 0; o >>= 1) v += __shfl_xor_sync(0xffffffffu, v, o);
    return v;
}
// packed gelu (tanh approx) on a channel pair
__device__ __forceinline__ ull gelu2(ull x) {
    ull x2 = mul2(x, x);
    ull ip = fma2(pk1(0.0356774081f), x2, pk1(0.7978845608f));
    ull up = mul2(x, ip);
    float u0, u1; upk(up, u0, u1);
    float t0, t1;
    asm("tanh.approx.f32 %0, %1;" : "=f"(t0) : "f"(u0));
    asm("tanh.approx.f32 %0, %1;" : "=f"(t1) : "f"(u1));
    ull tp = pk(t0, t1);
    ull hx = mul2(x, pk1(0.5f));
    return fma2(hx, tp, hx);
}

// ---------------- zero init + all-layer edge-weight constants ----------------
__global__ void zero_prep_kernel(const float* __restrict__ conv_w, int N, int B) {
    int i = blockIdx.x * blockDim.x + threadIdx.x;
    if (i < N) { g_deg[i] = 0; g_cur[i] = 0; }
    if (i < B * H) g_pool[i] = 0.0f;
    if (i < B) g_cnt[i] = 0;
    if (blockIdx.x == 0 && threadIdx.x < 96) {
        int w = threadIdx.x >> 5, lane = threadIdx.x & 31;
        const float* cw = conv_w + w * (H + 2) * H;
        float a0 = cw[64 * H + 2 * lane], a1 = cw[64 * H + 2 * lane + 1];
        float b0 = cw[65 * H + 2 * lane], b1 = cw[65 * H + 2 * lane + 1];
        float SW0 = warp_sum(a0 + a1);
        float SW1 = warp_sum(b0 + b1);
        float Q0  = warp_sum(a0 * a0 + a1 * a1);
        float Q1  = warp_sum(b0 * b0 + b1 * b1);
        float D01 = warp_sum(a0 * b0 + a1 * b1);
        if (lane == 0) {
            g_lc[w][0] = SW0; g_lc[w][1] = SW1; g_lc[w][2] = Q0;
            g_lc[w][3] = Q1;  g_lc[w][4] = D01;
        }
    }
}

// ---------------- node embedding MLP + fused hW0/stats0 (warp per node) ------
__global__ __launch_bounds__(256) void node_embed_kernel(
    const float* __restrict__ x,
    const float* __restrict__ w1, const float* __restrict__ b1,
    const float* __restrict__ g1, const float* __restrict__ be1,
    const float* __restrict__ w2, const float* __restrict__ b2,
    const float* __restrict__ g2, const float* __restrict__ be2,
    const float* __restrict__ cw0, const float* __restrict__ cb0, int N)
{
    __shared__ float ws[H * H];
    __shared__ float ws0[H * H];
    int t = threadIdx.x;
    for (int i = t; i < H * H; i += 256) { ws[i] = w2[i]; ws0[i] = cw0[i]; }
    __syncthreads();
    int node = blockIdx.x * 8 + (t >> 5);
    int lane = t & 31;
    if (node >= N) return;
    int c0 = 2 * lane, c1 = c0 + 1;
    float x0 = x[node * 2], x1 = x[node * 2 + 1];
    float p0 = fmaf(x1, w1[H + c0], fmaf(x0, w1[c0], b1[c0]));
    float p1 = fmaf(x1, w1[H + c1], fmaf(x0, w1[c1], b1[c1]));
    float s = warp_sum(p0 + p1);
    float q = warp_sum(p0 * p0 + p1 * p1);
    float mu = s * (1.0f / H);
    float r  = rsqrtf(q * (1.0f / H) - mu * mu + 1e-5f);
    ull ap = gelu2(fma2(pk(p0 - mu, p1 - mu), mul2(pk1(r), *(const ull*)&g1[c0]),
                        *(const ull*)&be1[c0]));
    float a0, a1; upk(ap, a0, a1);
    ull accp = *(const ull*)&b2[c0];
    #pragma unroll
    for (int k = 0; k < 32; k++) {
        float u = __shfl_sync(0xffffffffu, a0, k);
        float v = __shfl_sync(0xffffffffu, a1, k);
        ull w0 = *(const ull*)&ws[(2 * k) * H + c0];
        ull w1v = *(const ull*)&ws[(2 * k + 1) * H + c0];
        accp = fma2(pk1(u), w0, fma2(pk1(v), w1v, accp));
    }
    float acc0, acc1; upk(accp, acc0, acc1);
    s = warp_sum(acc0 + acc1);
    q = warp_sum(acc0 * acc0 + acc1 * acc1);
    mu = s * (1.0f / H);
    r  = rsqrtf(q * (1.0f / H) - mu * mu + 1e-5f);
    ull fp = gelu2(fma2(pk(acc0 - mu, acc1 - mu), mul2(pk1(r), *(const ull*)&g2[c0]),
                        *(const ull*)&be2[c0]));
    float f0, f1; upk(fp, f0, f1);
    *(ull*)&g_h[node * H + c0] = fp;
    // fused hW0 + stats0 (buffer 0)
    ull hwp = *(const ull*)&cb0[c0];
    #pragma unroll
    for (int k = 0; k < 32; k++) {
        float u = __shfl_sync(0xffffffffu, f0, k);
        float v = __shfl_sync(0xffffffffu, f1, k);
        ull w0 = *(const ull*)&ws0[(2 * k) * H + c0];
        ull w1v = *(const ull*)&ws0[(2 * k + 1) * H + c0];
        hwp = fma2(pk1(u), w0, fma2(pk1(v), w1v, hwp));
    }
    float hw0, hw1; upk(hwp, hw0, hw1);
    *(ull*)&g_hW[0][node * H + c0] = hwp;
    float w00 = cw0[64 * H + c0], w01 = cw0[64 * H + c1];
    float w10 = cw0[65 * H + c0], w11 = cw0[65 * H + c1];
    float S1 = warp_sum(hw0 + hw1);
    float S2 = warp_sum(hw0 * hw0 + hw1 * hw1);
    float D0 = warp_sum(hw0 * w00 + hw1 * w01);
    float D1 = warp_sum(hw0 * w10 + hw1 * w11);
    if (lane == 0) g_stats[0][node] = make_float4(S1, S2, D0, D1);
}

// ---------------- CSR build ----------------
__global__ void count_deg_kernel(const int* __restrict__ ei, int E) {
    int e = blockIdx.x * blockDim.x + threadIdx.x;
    if (e < E) atomicAdd(&g_deg[ei[E + e]], 1);
}

__global__ void scan_local_kernel(int N) {
    __shared__ int wsums[16];
    int t = threadIdx.x, lane = t & 31, w = t >> 5;
    int i = blockIdx.x * 512 + t;
    int x = (i < N) ? g_deg[i] : 0;
    int v = x;
    #pragma unroll
    for (int o = 1; o < 32; o <<= 1) { int n = __shfl_up_sync(0xffffffffu, v, o); if (lane >= o) v += n; }
    if (lane == 31) wsums[w] = v;
    __syncthreads();
    if (w == 0) {
        int s = (lane < 16) ? wsums[lane] : 0;
        #pragma unroll
        for (int o = 1; o < 16; o <<= 1) { int n = __shfl_up_sync(0xffffffffu, s, o); if (lane >= o) s += n; }
        if (lane < 16) wsums[lane] = s;
    }
    __syncthreads();
    int off = (w > 0) ? wsums[w - 1] : 0;
    int incl = v + off;
    if (i < N) g_off[i] = incl - x;
    if (t == 511) g_bsum[blockIdx.x] = incl;
}

__global__ void scan_bsum_kernel(int nblk) {
    __shared__ int wsums[8];
    int t = threadIdx.x, lane = t & 31, w = t >> 5;
    int x = (t < nblk) ? g_bsum[t] : 0;
    int v = x;
    #pragma unroll
    for (int o = 1; o < 32; o <<= 1) { int n = __shfl_up_sync(0xffffffffu, v, o); if (lane >= o) v += n; }
    if (lane == 31) wsums[w] = v;
    __syncthreads();
    if (w == 0) {
        int s = (lane < 8) ? wsums[lane] : 0;
        #pragma unroll
        for (int o = 1; o < 8; o <<= 1) { int n = __shfl_up_sync(0xffffffffu, s, o); if (lane >= o && lane < 8) s += n; }
        if (lane < 8) wsums[lane] = s;
    }
    __syncthreads();
    int off = (w > 0) ? wsums[w - 1] : 0;
    if (t < nblk) g_bsum[t] = v + off - x;   // exclusive
}

__global__ void scan_add_kernel(int N, int E) {
    int i = blockIdx.x * 512 + threadIdx.x;
    if (i < N) g_off[i] += g_bsum[blockIdx.x];
    if (i == 0) g_off[N] = E;
}

__global__ void fill_csr_kernel(const int* __restrict__ ei, const float* __restrict__ ea, int E) {
    int e = blockIdx.x * blockDim.x + threadIdx.x;
    if (e >= E) return;
    int d = ei[E + e];
    int p = g_off[d] + atomicAdd(&g_cur[d], 1);
    g_csr_src[p] = ei[e];
    g_csr_ea[p] = *(const float2*)&ea[2 * e];
}

// ---------------- per-layer: aggregate + residual/LN update (warp per dst) ---
// Prologue: lanes compute up-to-32 edges' LN scalars into smem; sweep loop
// broadcasts via LDS and gathers the hW row, all channel math in f32x2.
// Epilogue fuses next-layer hW/stats GEMM (or the global mean pool, last layer).
__global__ __launch_bounds__(256) void conv_agg_kernel(
    const float* __restrict__ cw,
    const float* __restrict__ mg, const float* __restrict__ mb,
    const float* __restrict__ ng, const float* __restrict__ nb,
    const float* __restrict__ og, const float* __restrict__ ob,
    const float* __restrict__ cwn, const float* __restrict__ cbn,
    const int* __restrict__ batch, int l, int do_pool, int N)
{
    __shared__ float  wsn[H * H];
    __shared__ float4 s_meta[8][32];
    __shared__ int    s_src[8][32];
    int t = threadIdx.x;
    if (!do_pool) {
        for (int i = t; i < H * H; i += 256) wsn[i] = cwn[i];
    }
    __syncthreads();
    int wid = t >> 5, lane = t & 31;
    int node = blockIdx.x * 8 + wid;
    if (node >= N) return;
    int rb = l & 1, wb = rb ^ 1;
    int c0 = 2 * lane, c1 = c0 + 1;
    ull We0p = *(const ull*)&cw[64 * H + c0];
    ull We1p = *(const ull*)&cw[65 * H + c0];
    ull mgp  = *(const ull*)&mg[c0];
    ull mbp  = *(const ull*)&mb[c0];
    float SW0 = g_lc[l][0], SW1 = g_lc[l][1], Q0 = g_lc[l][2], Q1 = g_lc[l][3], D01 = g_lc[l][4];
    int beg = g_off[node], end = g_off[node + 1];
    ull accp = pk(0.0f, 0.0f);
    const float* hWb = g_hW[rb];
    for (int base = beg; base < end; base += 32) {
        int cnt = min(32, end - base);
        if (lane < cnt) {
            int s = g_csr_src[base + lane];
            float2 ea = g_csr_ea[base + lane];
            float4 st = g_stats[rb][s];
            float sum = st.x + ea.x * SW0 + ea.y * SW1;
            float ssq = st.y + ea.x * ea.x * Q0 + ea.y * ea.y * Q1
                      + 2.0f * (ea.x * st.z + ea.y * st.w + ea.x * ea.y * D01);
            float mu = sum * (1.0f / H);
            float var = ssq * (1.0f / H) - mu * mu;
            s_meta[wid][lane] = make_float4(ea.x, ea.y, -mu, rsqrtf(var + 1e-5f));
            s_src[wid][lane] = s * H;
        }
        __syncwarp();
        #pragma unroll 4
        for (int j = 0; j < cnt; j++) {
            float4 m = s_meta[wid][j];       // LDS.128 broadcast
            int so = s_src[wid][j];          // LDS.32 broadcast
            ull hvp = *(const ull*)&hWb[so + c0];
            ull Ap = mul2(pk1(m.w), mgp);
            ull ep = fma2(pk1(m.x), We0p, fma2(pk1(m.y), We1p, pk1(m.z)));
            ull Kp = fma2(ep, Ap, mbp);
            ull argp = fma2(hvp, Ap, Kp);
            accp = add2(accp, gelu2(argp));
        }
        __syncwarp();
    }
    float acc0, acc1; upk(accp, acc0, acc1);
    float inv = 1.0f / fmaxf((float)(end - beg), 1.0f);
    float2 hrow = *(const float2*)&g_h[node * H + c0];
    float t0 = acc0 * inv + hrow.x;
    float t1 = acc1 * inv + hrow.y;
    float s1 = warp_sum(t0 + t1);
    float s2 = warp_sum(t0 * t0 + t1 * t1);
    float mu = s1 * (1.0f / H);
    float r  = rsqrtf(s2 * (1.0f / H) - mu * mu + 1e-5f);
    float co0 = (t0 - mu) * r * ng[c0] + nb[c0];
    float co1 = (t1 - mu) * r * ng[c1] + nb[c1];
    s1 = warp_sum(co0 + co1);
    s2 = warp_sum(co0 * co0 + co1 * co1);
    mu = s1 * (1.0f / H);
    r  = rsqrtf(s2 * (1.0f / H) - mu * mu + 1e-5f);
    float u0 = (co0 - mu) * r * og[c0] + ob[c0];
    float u1 = (co1 - mu) * r * og[c1] + ob[c1];
    float nh0 = hrow.x + u0, nh1 = hrow.y + u1;
    if (do_pool) {
        int b = batch[node];
        atomicAdd(&g_pool[b * H + c0], nh0);
        atomicAdd(&g_pool[b * H + c1], nh1);
        if (lane == 0) atomicAdd(&g_cnt[b], 1);
        return;
    }
    *(float2*)&g_h[node * H + c0] = make_float2(nh0, nh1);
    // fused next-layer hW + stats into buffer wb (packed GEMM)
    ull hwp = *(const ull*)&cbn[c0];
    #pragma unroll
    for (int k = 0; k < 32; k++) {
        float u = __shfl_sync(0xffffffffu, nh0, k);
        float v = __shfl_sync(0xffffffffu, nh1, k);
        ull w0 = *(const ull*)&wsn[(2 * k) * H + c0];
        ull w1v = *(const ull*)&wsn[(2 * k + 1) * H + c0];
        hwp = fma2(pk1(u), w0, fma2(pk1(v), w1v, hwp));
    }
    float hw0, hw1; upk(hwp, hw0, hw1);
    *(ull*)&g_hW[wb][node * H + c0] = hwp;
    float w00 = cwn[64 * H + c0], w01 = cwn[64 * H + c1];
    float w10 = cwn[65 * H + c0], w11 = cwn[65 * H + c1];
    float S1 = warp_sum(hw0 + hw1);
    float S2 = warp_sum(hw0 * hw0 + hw1 * hw1);
    float D0 = warp_sum(hw0 * w00 + hw1 * w01);
    float D1 = warp_sum(hw0 * w10 + hw1 * w11);
    if (lane == 0) g_stats[wb][node] = make_float4(S1, S2, D0, D1);
}

// ---------------- head MLP (warp per graph) ----------------
__global__ __launch_bounds__(256) void head_kernel(
    const float* __restrict__ w1, const float* __restrict__ b1,
    const float* __restrict__ gg1, const float* __restrict__ bb1,
    const float* __restrict__ w2, const float* __restrict__ b2,
    const float* __restrict__ gg2, const float* __restrict__ bb2,
    const float* __restrict__ w3, const float* __restrict__ b3,
    float* __restrict__ out, int B)
{
    int t = threadIdx.x;
    int g = blockIdx.x * 8 + (t >> 5);
    int lane = t & 31;
    if (g >= B) return;
    float inv = 1.0f / fmaxf((float)g_cnt[g], 1.0f);
    int c0 = 2 * lane, c1 = c0 + 1;
    float v0 = g_pool[g * H + c0] * inv;
    float v1 = g_pool[g * H + c1] * inv;
    float acc0 = b1[c0], acc1 = b1[c1];
    #pragma unroll
    for (int k = 0; k < 32; k++) {
        float a = __shfl_sync(0xffffffffu, v0, k);
        float b_ = __shfl_sync(0xffffffffu, v1, k);
        acc0 = fmaf(a, w1[(2 * k) * H + c0], acc0); acc0 = fmaf(b_, w1[(2 * k + 1) * H + c0], acc0);
        acc1 = fmaf(a, w1[(2 * k) * H + c1], acc1); acc1 = fmaf(b_, w1[(2 * k + 1) * H + c1], acc1);
    }
    float s1 = warp_sum(acc0 + acc1);
    float s2 = warp_sum(acc0 * acc0 + acc1 * acc1);
    float mu = s1 * (1.0f / H);
    float r  = rsqrtf(s2 * (1.0f / H) - mu * mu + 1e-5f);
    float a0 = fmaxf((acc0 - mu) * r * gg1[c0] + bb1[c0], 0.0f);
    float a1 = fmaxf((acc1 - mu) * r * gg1[c1] + bb1[c1], 0.0f);
    float acc = b2[lane];
    #pragma unroll
    for (int k = 0; k < 32; k++) {
        float a = __shfl_sync(0xffffffffu, a0, k);
        float bb = __shfl_sync(0xffffffffu, a1, k);
        acc = fmaf(a, w2[(2 * k) * 32 + lane], acc);
        acc = fmaf(bb, w2[(2 * k + 1) * 32 + lane], acc);
    }
    s1 = warp_sum(acc);
    s2 = warp_sum(acc * acc);
    mu = s1 * (1.0f / 32.0f);
    r  = rsqrtf(s2 * (1.0f / 32.0f) - mu * mu + 1e-5f);
    float z = fmaxf((acc - mu) * r * gg2[lane] + bb2[lane], 0.0f);
    float o = warp_sum(z * w3[lane]);
    if (lane == 0) out[g] = o + b3[0];
}

// ---------------- launch ----------------
extern "C" void kernel_launch(void* const* d_in, const int* in_sizes, int n_in,
                              void* d_out, int out_size)
{
    const float* x        = (const float*)d_in[0];
    const float* edge_attr= (const float*)d_in[1];
    const float* ne_w1 = (const float*)d_in[2];
    const float* ne_b1 = (const float*)d_in[3];
    const float* ne_g1 = (const float*)d_in[4];
    const float* ne_be1= (const float*)d_in[5];
    const float* ne_w2 = (const float*)d_in[6];
    const float* ne_b2 = (const float*)d_in[7];
    const float* ne_g2 = (const float*)d_in[8];
    const float* ne_be2= (const float*)d_in[9];
    const float* conv_w = (const float*)d_in[10];
    const float* conv_b = (const float*)d_in[11];
    const float* conv_mg= (const float*)d_in[12];
    const float* conv_mb= (const float*)d_in[13];
    const float* conv_ng= (const float*)d_in[14];
    const float* conv_nb= (const float*)d_in[15];
    const float* out_ng = (const float*)d_in[16];
    const float* out_nb = (const float*)d_in[17];
    const float* m_w1 = (const float*)d_in[18];
    const float* m_b1 = (const float*)d_in[19];
    const float* m_g1 = (const float*)d_in[20];
    const float* m_be1= (const float*)d_in[21];
    const float* m_w2 = (const float*)d_in[22];
    const float* m_b2 = (const float*)d_in[23];
    const float* m_g2 = (const float*)d_in[24];
    const float* m_be2= (const float*)d_in[25];
    const float* m_w3 = (const float*)d_in[26];
    const float* m_b3 = (const float*)d_in[27];
    const int* edge_index = (const int*)d_in[28];
    const int* batch      = (const int*)d_in[29];

    int N = in_sizes[0] / 2;
    int E = in_sizes[1] / 2;
    int B = out_size;

    int NB8  = (N + 7) / 8;
    int EB   = (E + 255) / 256;
    int nscan = (N + 511) / 512;

    zero_prep_kernel<<<(N + 255) / 256, 256>>>(conv_w, N, B);
    node_embed_kernel<<<NB8, 256>>>(x, ne_w1, ne_b1, ne_g1, ne_be1,
                                    ne_w2, ne_b2, ne_g2, ne_be2,
                                    conv_w, conv_b, N);
    count_deg_kernel<<<EB, 256>>>(edge_index, E);
    scan_local_kernel<<<nscan, 512>>>(N);
    scan_bsum_kernel<<<1, 256>>>(nscan);
    scan_add_kernel<<<nscan, 512>>>(N, E);
    fill_csr_kernel<<<EB, 256>>>(edge_index, edge_attr, E);

    for (int l = 0; l < 3; l++) {
        const float* cw  = conv_w + l * (H + 2) * H;
        const float* cwn = conv_w + ((l + 1) % 3) * (H + 2) * H;
        const float* cbn = conv_b + ((l + 1) % 3) * H;
        conv_agg_kernel<<<NB8, 256>>>(cw,
            conv_mg + l * H, conv_mb + l * H,
            conv_ng + l * H, conv_nb + l * H,
            out_ng + l * H, out_nb + l * H,
            cwn, cbn, batch, l, (l == 2) ? 1 : 0, N);
    }

    head_kernel<<<(B + 7) / 8, 256>>>(m_w1, m_b1, m_g1, m_be1,
                                      m_w2, m_b2, m_g2, m_be2,
                                      m_w3, m_b3, (float*)d_out, B);
}